// round 11
// baseline (speedup 1.0000x reference)
#include <cuda_runtime.h>
#include <cstdint>

// Problem constants (B=8192, T=512, H=W=64)
#define WIDTH   64
#define HW      4096
#define BB      8192        // max batches (static scratch sizing)
#define TT      512
#define NB      16          // batches per rollout block
#define NTHREADS 128
#define CHUNK   64
#define SPAD    65
#define RPAD    65

// -------- device scratch (pre-packed world + actions) --------
__device__ uint32_t g_wall[BB * 128];        // 1 bit/cell, 128 words/batch (4 MB)
__device__ uint32_t g_goal[BB * 128];        // 4 MB
__device__ uint32_t g_act [BB * TT / 4];     // actions as bytes (4 MB)

// ============ Kernel 1: pack world -> bitmaps, actions -> bytes ============
// One warp handles 1024 consecutive cells of one batch: 32 ballots of 32 cells.
// Ballot u lives in lane u after shuffle -> each lane stores exactly one word,
// giving a fully coalesced 128B store per warp per array.
__global__ __launch_bounds__(256)
void pack_kernel(const float* __restrict__ world,
                 const int*   __restrict__ a,
                 int B, int T)
{
    const int lane    = threadIdx.x & 31;
    const int warp_g  = (blockIdx.x * blockDim.x + threadIdx.x) >> 5;
    const int nwarps  = (gridDim.x * blockDim.x) >> 5;

    // chunk = 1024 cells (32 words) of one batch; 4 chunks per batch.
    const int nchunks = B * (HW / 1024);
    for (int ch = warp_g; ch < nchunks; ch += nwarps) {
        const int b = ch >> 2;
        const int c = ch & 3;
        const float* wallp = world + (size_t)b * 2 * HW + c * 1024;
        const float* goalp = wallp + HW;

        uint32_t myw = 0, myg = 0;
        #pragma unroll
        for (int u = 0; u < 32; u++) {
            float wv = wallp[u * 32 + lane];
            float gv = goalp[u * 32 + lane];
            uint32_t bw = __ballot_sync(0xffffffffu, wv == 1.0f);
            uint32_t bg = __ballot_sync(0xffffffffu, gv == 10.0f);
            // keep ballot u in lane u
            if (lane == u) { myw = bw; myg = bg; }
        }
        g_wall[b * 128 + c * 32 + lane] = myw;
        g_goal[b * 128 + c * 32 + lane] = myg;
    }

    // Actions: int32 -> byte, 4 at a time.
    const int tidg   = blockIdx.x * blockDim.x + threadIdx.x;
    const int stride = gridDim.x * blockDim.x;
    const int total4 = (B * T) / 4;
    const int4* ap = reinterpret_cast<const int4*>(a);
    for (int i = tidg; i < total4; i += stride) {
        int4 v = ap[i];
        g_act[i] = (uint32_t)(v.x & 0xff)
                 | ((uint32_t)(v.y & 0xff) << 8)
                 | ((uint32_t)(v.z & 0xff) << 16)
                 | ((uint32_t)(v.w & 0xff) << 24);
    }
}

// ============ Kernel 2: rollout from packed bitmaps ============
// smem: swall[NB*128] + sgoal[NB*128] + sact[NB*T/4] + stage_s + stage_r
__global__ __launch_bounds__(NTHREADS, 1)
void rollout_kernel(const float* __restrict__ s0,
                    float* __restrict__ out_s,   // [B, T+1, 2]
                    float* __restrict__ out_r,   // [B, T+1]
                    int B, int T)
{
    extern __shared__ unsigned char smem[];
    uint32_t* swall   = reinterpret_cast<uint32_t*>(smem);             // NB*128
    uint32_t* sgoal   = swall + NB * 128;                              // NB*128
    uint32_t* sactw   = sgoal + NB * 128;                              // NB*T/4
    float2*   stage_s = reinterpret_cast<float2*>(sactw + NB * TT / 4);// NB*SPAD
    float*    stage_r = reinterpret_cast<float*>(stage_s + NB * SPAD); // NB*RPAD

    const int b0  = blockIdx.x * NB;
    const int tid = threadIdx.x;

    // ---- stage packed data (mostly L2 hits) ----
    {
        const uint4* gw = reinterpret_cast<const uint4*>(&g_wall[b0 * 128]);
        const uint4* gg = reinterpret_cast<const uint4*>(&g_goal[b0 * 128]);
        uint4* sw = reinterpret_cast<uint4*>(swall);
        uint4* sg = reinterpret_cast<uint4*>(sgoal);
        #pragma unroll
        for (int n = 0; n < (NB * 128 / 4) / NTHREADS; n++) {
            int i = tid + n * NTHREADS;
            sw[i] = gw[i];
            sg[i] = gg[i];
        }
        const uint4* ga = reinterpret_cast<const uint4*>(&g_act[b0 * (TT / 4)]);
        uint4* sa = reinterpret_cast<uint4*>(sactw);
        #pragma unroll
        for (int n = 0; n < (NB * TT / 16) / NTHREADS; n++) {
            int i = tid + n * NTHREADS;
            sa[i] = ga[i];
        }
    }
    __syncthreads();

    // ---- rollout state ----
    int si = 0, sj = 0;
    const bool roller = (tid < NB) && (b0 + tid < B);
    const uint32_t* mywall = swall + tid * 128;
    const uint32_t* mygoal = sgoal + tid * 128;
    const uint8_t*  myact  = reinterpret_cast<const uint8_t*>(sactw) + (size_t)tid * TT;

    if (roller) {
        const int b = b0 + tid;
        si = (int)s0[2 * b + 0];
        sj = (int)s0[2 * b + 1];
        reinterpret_cast<float2*>(out_s)[(size_t)b * (T + 1)] =
            make_float2((float)si, (float)sj);
        out_r[(size_t)b * (T + 1)] = 0.0f;
    }

    for (int c0 = 0; c0 < T; c0 += CHUNK) {
        if (roller) {
            float2* ss = stage_s + tid * SPAD;
            float*  sr = stage_r + tid * RPAD;
            int at = myact[c0];
            #pragma unroll 4
            for (int k = 0; k < CHUNK; k++) {
                int t = c0 + k;
                int at_next = (t + 1 < T) ? myact[t + 1] : 0;
                int dr = (at == 1 ? -1 : 0) + (at == 2 ? 1 : 0);
                int dc = (at == 3 ? -1 : 0) + (at == 4 ? 1 : 0);
                int ni = si + dr;
                int nj = sj + dc;
                int idx = ni * WIDTH + nj;
                // JAX take_along_axis: negative wraps (+HW); outside [-HW,HW)
                // -> NaN fill -> neither goal nor wall -> -0.01, move accepted.
                int  eidx  = (idx < 0) ? idx + HW : idx;
                bool valid = ((unsigned)eidx) < (unsigned)HW;
                int  cidx  = valid ? eidx : 0;          // branchless: safe read
                uint32_t wallw = mywall[cidx >> 5];
                uint32_t goalw = mygoal[cidx >> 5];
                uint32_t bit   = 1u << (cidx & 31);
                bool goal = valid && ((goalw & bit) != 0u);
                bool wall = valid && !goal && ((wallw & bit) != 0u);
                float r = goal ? 1.0f : (wall ? -1.0f : -0.01f);
                if (!wall) { si = ni; sj = nj; }
                ss[k] = make_float2((float)si, (float)sj);
                sr[k] = r;
                at = at_next;
            }
        }
        __syncthreads();

        // ---- coalesced flush ----
        {
            const int steps = min(CHUNK, T - c0);
            #pragma unroll
            for (int n = 0; n < (NB * CHUNK) / NTHREADS; n++) {
                int g  = tid + n * NTHREADS;
                int bi = g >> 6;          // g / CHUNK
                int k  = g & (CHUNK - 1);
                int b  = b0 + bi;
                if (b < B && k < steps) {
                    reinterpret_cast<float2*>(out_s)[(size_t)b * (T + 1) + c0 + 1 + k] =
                        stage_s[bi * SPAD + k];
                    out_r[(size_t)b * (T + 1) + c0 + 1 + k] = stage_r[bi * RPAD + k];
                }
            }
        }
        __syncthreads();
    }
}

extern "C" void kernel_launch(void* const* d_in, const int* in_sizes, int n_in,
                              void* d_out, int out_size)
{
    const float* s0    = (const float*)d_in[0];   // [B, 2]
    const int*   a     = (const int*)  d_in[1];   // [B, T]
    const float* world = (const float*)d_in[2];   // [B, 2, 64, 64]

    const int B = in_sizes[0] / 2;
    const int T = in_sizes[1] / B;

    float* out_s = (float*)d_out;                       // [B, T+1, 2]
    float* out_r = out_s + (size_t)B * (T + 1) * 2;     // [B, T+1]

    pack_kernel<<<592, 256>>>(world, a, B, T);

    const int smem_bytes = NB * 128 * 4 * 2       // wall + goal bitmaps
                         + NB * TT                // actions (bytes)
                         + NB * SPAD * 8 + NB * RPAD * 4;  // ~37 KB
    const int grid = (B + NB - 1) / NB;                 // 512
    rollout_kernel<<<grid, NTHREADS, smem_bytes>>>(s0, out_s, out_r, B, T);
}

// round 13
// speedup vs baseline: 1.3631x; 1.3631x over previous
#include <cuda_runtime.h>
#include <cstdint>

// Problem constants (B=8192, T=512, H=W=64)
#define WIDTH    64
#define HW       4096
#define TT       512
#define NB       16          // batches per block
#define NTHREADS 128
#define CHUNK    64
#define SPAD     65
#define RPAD     65

// cp.async ring: tile = 8 KB (2048 floats), 4 tiles per batch
// (wall half0, wall half1, goal half0, goal half1), ring depth 8.
#define TILE_FLOATS 2048
#define TILE_BYTES  8192
#define DEPTH       8
#define NTILES      (NB * 4)

// ---- cp.async helpers ----
__device__ __forceinline__ void cp_async16(uint32_t dst_smem, const void* src) {
    asm volatile(
        "{\n\t.reg .u64 g;\n\tcvta.to.global.u64 g, %1;\n\t"
        "cp.async.cg.shared.global [%0], [g], 16;\n\t}\n"
        :: "r"(dst_smem), "l"(src) : "memory");
}
__device__ __forceinline__ void cp_async_commit() {
    asm volatile("cp.async.commit_group;" ::: "memory");
}
template <int N>
__device__ __forceinline__ void cp_async_wait() {
    asm volatile("cp.async.wait_group %0;" :: "n"(N) : "memory");
}

// smem layout:
//   ring   : DEPTH * TILE_BYTES            = 64 KB
//   map2   : NB * 256 uint32 (2 bits/cell) = 16 KB
//   acts   : NB * TT bytes                 =  8 KB
//   stage_s: NB * SPAD float2              = 8320 B
//   stage_r: NB * RPAD float               = 4160 B
#define SMEM_RING  0
#define SMEM_MAP   (DEPTH * TILE_BYTES)
#define SMEM_ACT   (SMEM_MAP + NB * 256 * 4)
#define SMEM_SS    (SMEM_ACT + NB * TT)
#define SMEM_SR    (SMEM_SS + NB * SPAD * 8)
#define SMEM_TOTAL (SMEM_SR + NB * RPAD * 4)

__global__ __launch_bounds__(NTHREADS)
void rollout_fused_kernel(const float* __restrict__ s0,
                          const int*   __restrict__ a,
                          const float* __restrict__ world,
                          float* __restrict__ out_s,   // [B, T+1, 2]
                          float* __restrict__ out_r,   // [B, T+1]
                          int B, int T)
{
    extern __shared__ unsigned char smem[];
    float*    ring    = reinterpret_cast<float*>(smem + SMEM_RING);
    uint32_t* map2    = reinterpret_cast<uint32_t*>(smem + SMEM_MAP);
    uint8_t*  acts    = smem + SMEM_ACT;
    float2*   stage_s = reinterpret_cast<float2*>(smem + SMEM_SS);
    float*    stage_r = reinterpret_cast<float*>(smem + SMEM_SR);

    const int b0  = blockIdx.x * NB;
    const int tid = threadIdx.x;
    const uint32_t ring_base = (uint32_t)__cvta_generic_to_shared(ring);

    // ---------- Phase 1b: stage actions as bytes (LDGs overlap the ring) ----
    {
        const int total4 = (NB * TT) / 4;
        const int4* ap = reinterpret_cast<const int4*>(a + (size_t)b0 * TT);
        uint32_t* actw = reinterpret_cast<uint32_t*>(acts);
        const int maxb = B - b0;
        #pragma unroll
        for (int n = 0; n < total4 / NTHREADS; n++) {
            int i  = tid + n * NTHREADS;
            int bi = (i * 4) / TT;
            uint32_t packed = 0;
            if (bi < maxb) {
                int4 v = ap[i];
                packed = (uint32_t)(v.x & 0xff)
                       | ((uint32_t)(v.y & 0xff) << 8)
                       | ((uint32_t)(v.z & 0xff) << 16)
                       | ((uint32_t)(v.w & 0xff) << 24);
            }
            actw[i] = packed;
        }
    }

    // ---------- Phase 1a: cp.async ring world -> 2-bit map ----------
    // tile t: batch bi = t>>2, p = t&3; plane = p>>1 (0 wall / 1 goal),
    // half = p&1 (cells [half*2048, half*2048+2048)).
    const float* wbase = world + (size_t)b0 * 2 * HW;

    // prologue: issue first DEPTH tiles (one commit-group per tile)
    #pragma unroll
    for (int t = 0; t < DEPTH; t++) {
        if (b0 + (t >> 2) < B) {
            const float* gsrc = wbase + (size_t)(t >> 2) * 2 * HW
                              + ((t >> 1) & 1) * HW + (t & 1) * TILE_FLOATS;
            uint32_t dst = ring_base + (t & (DEPTH - 1)) * TILE_BYTES;
            #pragma unroll
            for (int k = 0; k < 4; k++) {
                int i4 = tid + k * NTHREADS;      // float4 index within tile
                cp_async16(dst + i4 * 16, gsrc + i4 * 4);
            }
        }
        cp_async_commit();
    }

    for (int t = 0; t < NTILES; t++) {
        cp_async_wait<DEPTH - 1>();   // tile t landed (see unconditional commit!)
        __syncthreads();

        // pack tile t: thread tid packs cells [tid*16, tid*16+16) of the half
        const int bi    = t >> 2;
        const int plane = (t >> 1) & 1;
        const int half  = t & 1;
        if (b0 + bi < B) {
            const float4* tf = reinterpret_cast<const float4*>(
                ring + (size_t)(t & (DEPTH - 1)) * TILE_FLOATS);
            const float target = plane ? 10.0f : 1.0f;
            uint32_t packed = 0;
            #pragma unroll
            for (int j = 0; j < 4; j++) {
                float4 v = tf[tid * 4 + j];
                uint32_t bits = (v.x == target ? 1u : 0u)
                              | (v.y == target ? 4u : 0u)
                              | (v.z == target ? 16u : 0u)
                              | (v.w == target ? 64u : 0u);
                packed |= bits << (8 * j);       // cell c at bit 2c
            }
            const int widx = bi * 256 + half * 128 + tid;
            if (plane == 0) map2[widx] = packed;          // wall -> bit 2c
            else            map2[widx] |= packed << 1;    // goal -> bit 2c+1
        }
        __syncthreads();   // pack reads done before slot reuse

        const int tn = t + DEPTH;
        if (tn < NTILES && b0 + (tn >> 2) < B) {
            const float* gsrc = wbase + (size_t)(tn >> 2) * 2 * HW
                              + ((tn >> 1) & 1) * HW + (tn & 1) * TILE_FLOATS;
            uint32_t dst = ring_base + (tn & (DEPTH - 1)) * TILE_BYTES;
            #pragma unroll
            for (int k = 0; k < 4; k++) {
                int i4 = tid + k * NTHREADS;
                cp_async16(dst + i4 * 16, gsrc + i4 * 4);
            }
        }
        // UNCONDITIONAL commit: keeps the "group t == tile t" alignment so
        // wait_group<DEPTH-1> at iteration t always proves tile t landed,
        // including the last DEPTH iterations (empty groups are legal).
        cp_async_commit();
    }
    cp_async_wait<0>();
    __syncthreads();

    // ---------- Phase 2: branchless rollout, rollers spread over 4 warps ----
    const int wid  = tid >> 5;
    const int lane = tid & 31;
    const int bi   = wid * 4 + lane;                 // valid when lane < 4
    const bool roller = (lane < 4) && (b0 + bi < B);

    int si = 0, sj = 0;
    const uint32_t* mymap = map2 + bi * 256;
    const uint8_t*  myact = acts + (size_t)bi * TT;

    if (roller) {
        const int b = b0 + bi;
        si = (int)s0[2 * b + 0];
        sj = (int)s0[2 * b + 1];
        reinterpret_cast<float2*>(out_s)[(size_t)b * (T + 1)] =
            make_float2((float)si, (float)sj);
        out_r[(size_t)b * (T + 1)] = 0.0f;
    }

    for (int c0 = 0; c0 < T; c0 += CHUNK) {
        if (roller) {
            float2* ss = stage_s + bi * SPAD;
            float*  sr = stage_r + bi * RPAD;
            int at = myact[c0];
            #pragma unroll 4
            for (int k = 0; k < CHUNK; k++) {
                int t = c0 + k;
                int at_next = (t + 1 < T) ? myact[t + 1] : 0;
                int dr = (at == 2) - (at == 1);
                int dc = (at == 4) - (at == 3);
                int ni = si + dr;
                int nj = sj + dc;
                int idx  = ni * WIDTH + nj;
                // JAX take_along_axis: negative wraps (+HW); outside [-HW,HW)
                // -> fill(NaN) -> neither goal nor wall -> -0.01, move accepted.
                int eidx = idx + (HW & (idx >> 31));           // wrap negatives
                uint32_t maskv = ((unsigned)eidx < (unsigned)HW) ? 3u : 0u;
                int cidx = eidx & (HW - 1);                    // safe read
                uint32_t word = mymap[cidx >> 4];
                uint32_t code = (word >> ((cidx & 15) * 2)) & maskv;
                bool blocked = (code == 1u);                   // wall & !goal
                si = blocked ? si : ni;
                sj = blocked ? sj : nj;
                float r = (code >= 2u) ? 1.0f : (blocked ? -1.0f : -0.01f);
                ss[k] = make_float2((float)si, (float)sj);
                sr[k] = r;
                at = at_next;
            }
        }
        __syncthreads();

        // ---- coalesced flush ----
        {
            const int steps = min(CHUNK, T - c0);
            #pragma unroll
            for (int n = 0; n < (NB * CHUNK) / NTHREADS; n++) {
                int g   = tid + n * NTHREADS;
                int fbi = g >> 6;            // g / CHUNK
                int k   = g & (CHUNK - 1);
                int b   = b0 + fbi;
                if (b < B && k < steps) {
                    reinterpret_cast<float2*>(out_s)[(size_t)b * (T + 1) + c0 + 1 + k] =
                        stage_s[fbi * SPAD + k];
                    out_r[(size_t)b * (T + 1) + c0 + 1 + k] = stage_r[fbi * RPAD + k];
                }
            }
        }
        __syncthreads();
    }
}

extern "C" void kernel_launch(void* const* d_in, const int* in_sizes, int n_in,
                              void* d_out, int out_size)
{
    const float* s0    = (const float*)d_in[0];   // [B, 2]
    const int*   a     = (const int*)  d_in[1];   // [B, T]
    const float* world = (const float*)d_in[2];   // [B, 2, 64, 64]

    const int B = in_sizes[0] / 2;
    const int T = in_sizes[1] / B;

    float* out_s = (float*)d_out;                       // [B, T+1, 2]
    float* out_r = out_s + (size_t)B * (T + 1) * 2;     // [B, T+1]

    cudaFuncSetAttribute(rollout_fused_kernel,
                         cudaFuncAttributeMaxDynamicSharedMemorySize, SMEM_TOTAL);

    const int grid = (B + NB - 1) / NB;                 // 512
    rollout_fused_kernel<<<grid, NTHREADS, SMEM_TOTAL>>>(s0, a, world,
                                                         out_s, out_r, B, T);
}

// round 17
// speedup vs baseline: 1.5403x; 1.1299x over previous
#include <cuda_runtime.h>
#include <cstdint>

// Problem constants (B=8192, T=512, H=W=64)
#define WIDTH    64
#define HW       4096
#define TT       512
#define NB       64          // batches per block
#define NTHREADS 256
#define CHUNK    64
#define SPAD     65          // padded stride for stage arrays
#define DEPTH    4           // cp.async ring depth (tiles)
#define TILE_FLOATS 4096     // one plane (wall or goal) of one batch = 16 KB

// smem layout (bytes):
//   maps : NB*256*4 = 64 KB                      [0, 65536)
//   union at 65536 (64 KB):
//     ring    : DEPTH*TILE_FLOATS*4 = 64 KB      (phase 1 only)
//     stage_s : NB*SPAD*8 = 33280                (phase 2 only)
//     stage_r : NB*SPAD*4 = 16640                (phase 2 only)
#define SMEM_MAPS  0
#define SMEM_RING  65536
#define SMEM_SS    65536
#define SMEM_SR    (65536 + NB * SPAD * 8)
#define SMEM_TOTAL (65536 + 65536)

// ---- cp.async helpers ----
__device__ __forceinline__ void cp_async16(uint32_t dst_smem, const void* src) {
    asm volatile(
        "{\n\t.reg .u64 g;\n\tcvta.to.global.u64 g, %1;\n\t"
        "cp.async.cg.shared.global [%0], [g], 16;\n\t}\n"
        :: "r"(dst_smem), "l"(src) : "memory");
}
__device__ __forceinline__ void cp_async_commit() {
    asm volatile("cp.async.commit_group;" ::: "memory");
}
template <int N>
__device__ __forceinline__ void cp_async_wait() {
    asm volatile("cp.async.wait_group %0;" :: "n"(N) : "memory");
}

__global__ __launch_bounds__(NTHREADS)
void rollout_fused_kernel(const float* __restrict__ s0,
                          const int*   __restrict__ a,
                          const float* __restrict__ world,
                          float* __restrict__ out_s,   // [B, T+1, 2]
                          float* __restrict__ out_r,   // [B, T+1]
                          int B, int T)
{
    extern __shared__ unsigned char smem[];
    uint32_t* maps    = reinterpret_cast<uint32_t*>(smem + SMEM_MAPS);
    float*    ring    = reinterpret_cast<float*>(smem + SMEM_RING);
    float2*   stage_s = reinterpret_cast<float2*>(smem + SMEM_SS);
    float*    stage_r = reinterpret_cast<float*>(smem + SMEM_SR);

    const int b0   = blockIdx.x * NB;
    const int tid  = threadIdx.x;
    const int maxb = min(NB, B - b0);
    const uint32_t ring_base = (uint32_t)__cvta_generic_to_shared(ring);

    // ================= Phase 1: bar-free stream + pack =================
    // Tile t: batch bi = t>>1, plane = t&1 (0 wall, 1 goal). One plane/tile.
    // Thread tid copies float4s {tid, tid+256, tid+512, tid+768} of the tile
    // and later packs exactly those float4s -> per-thread wait_group suffices,
    // no __syncthreads anywhere in this loop.
    #pragma unroll
    for (int t = 0; t < DEPTH; t++) {
        const int bi = t >> 1, plane = t & 1;
        if (bi < maxb) {
            const float4* gsrc = reinterpret_cast<const float4*>(
                world + (size_t)(b0 + bi) * 2 * HW + plane * HW);
            uint32_t dst = ring_base + (t & (DEPTH - 1)) * (TILE_FLOATS * 4);
            #pragma unroll
            for (int k = 0; k < 4; k++) {
                int i4 = tid + k * NTHREADS;
                cp_async16(dst + i4 * 16, gsrc + i4);
            }
        }
        cp_async_commit();
    }

    uint32_t wallv[4];
    const int sub   = tid & 3;
    const int shift = sub * 8;

    for (int t = 0; t < 2 * NB; t++) {
        cp_async_wait<DEPTH - 1>();   // tile t landed (commit every iteration)

        const int bi = t >> 1, plane = t & 1;
        if (bi < maxb) {
            const float4* tf = reinterpret_cast<const float4*>(
                ring + (size_t)(t & (DEPTH - 1)) * TILE_FLOATS);
            const float target = plane ? 10.0f : 1.0f;
            #pragma unroll
            for (int j = 0; j < 4; j++) {
                float4 v = tf[j * NTHREADS + tid];       // conflict-free LDS.128
                // cells 4*(j*256+tid)+{0..3}; 2 bits/cell spacing
                uint32_t nib = (v.x == target ? 1u : 0u)
                             | (v.y == target ? 4u : 0u)
                             | (v.z == target ? 16u : 0u)
                             | (v.w == target ? 64u : 0u);
                uint32_t val = nib << shift;
                val |= __shfl_xor_sync(0xffffffffu, val, 1);
                val |= __shfl_xor_sync(0xffffffffu, val, 2);
                if (plane == 0) {
                    wallv[j] = val;                       // hold until goal tile
                } else if (sub == 0) {
                    // word w = j*64 + tid/4 of batch bi; wall bit 2c, goal 2c+1
                    maps[bi * 256 + j * 64 + (tid >> 2)] = wallv[j] | (val << 1);
                }
            }
        }

        const int tn = t + DEPTH;
        if (tn < 2 * NB && (tn >> 1) < maxb) {
            const float4* gsrc = reinterpret_cast<const float4*>(
                world + (size_t)(b0 + (tn >> 1)) * 2 * HW + (tn & 1) * HW);
            uint32_t dst = ring_base + (tn & (DEPTH - 1)) * (TILE_FLOATS * 4);
            #pragma unroll
            for (int k = 0; k < 4; k++) {
                int i4 = tid + k * NTHREADS;
                cp_async16(dst + i4 * 16, gsrc + i4);
            }
        }
        cp_async_commit();   // unconditional: keeps group<->tile alignment
    }
    __syncthreads();         // maps complete & visible; ring dead -> stage reuse

    // ================= Phase 2: 32-wide rollout + coalesced flush =========
    const int wid  = tid >> 5;
    const int lane = tid & 31;
    const int bi   = wid * 32 + lane;                 // warps 0,1 -> bi 0..63
    const bool roller = (wid < 2) && (bi < maxb);

    int si = 0, sj = 0;
    const uint32_t* mymap = maps + bi * 256;
    const int*      myact = a + (size_t)(b0 + bi) * TT;

    if (roller) {
        const int b = b0 + bi;
        si = (int)s0[2 * b + 0];
        sj = (int)s0[2 * b + 1];
        reinterpret_cast<float2*>(out_s)[(size_t)b * (T + 1)] =
            make_float2((float)si, (float)sj);
        out_r[(size_t)b * (T + 1)] = 0.0f;
    }

    for (int c0 = 0; c0 < T; c0 += CHUNK) {
        if (roller) {
            float2* ss = stage_s + bi * SPAD;
            float*  sr = stage_r + bi * SPAD;
            // 2-step action lookahead (actions independent of state chain)
            int a0 = __ldg(myact + c0);
            int a1 = __ldg(myact + min(c0 + 1, T - 1));
            #pragma unroll 4
            for (int k = 0; k < CHUNK; k++) {
                const int t = c0 + k;
                int a2 = __ldg(myact + min(t + 2, T - 1));
                int dr = (a0 == 2) - (a0 == 1);
                int dc = (a0 == 4) - (a0 == 3);
                int ni = si + dr;
                int nj = sj + dc;
                int idx  = ni * WIDTH + nj;
                // JAX take_along_axis: negative wraps (+HW); outside [-HW,HW)
                // -> fill(NaN) -> neither goal nor wall -> -0.01, move accepted.
                int eidx = idx + (HW & (idx >> 31));
                uint32_t maskv = ((unsigned)eidx < (unsigned)HW) ? 3u : 0u;
                int cidx = eidx & (HW - 1);
                uint32_t word = mymap[cidx >> 4];
                uint32_t code = (word >> ((cidx & 15) * 2)) & maskv;
                bool blocked = (code == 1u);              // wall & !goal
                si = blocked ? si : ni;
                sj = blocked ? sj : nj;
                float r = (code >= 2u) ? 1.0f : (blocked ? -1.0f : -0.01f);
                ss[k] = make_float2((float)si, (float)sj);
                sr[k] = r;
                a0 = a1; a1 = a2;
            }
        }
        __syncthreads();

        // ---- coalesced flush: NB*CHUNK = 4096 elements, 16 iterations ----
        {
            const int steps = min(CHUNK, T - c0);
            #pragma unroll
            for (int n = 0; n < (NB * CHUNK) / NTHREADS; n++) {
                int g   = tid + n * NTHREADS;
                int fbi = g >> 6;            // g / CHUNK
                int k   = g & (CHUNK - 1);
                if (fbi < maxb && k < steps) {
                    const int b = b0 + fbi;
                    reinterpret_cast<float2*>(out_s)[(size_t)b * (T + 1) + c0 + 1 + k] =
                        stage_s[fbi * SPAD + k];
                    out_r[(size_t)b * (T + 1) + c0 + 1 + k] = stage_r[fbi * SPAD + k];
                }
            }
        }
        __syncthreads();
    }
}

extern "C" void kernel_launch(void* const* d_in, const int* in_sizes, int n_in,
                              void* d_out, int out_size)
{
    const float* s0    = (const float*)d_in[0];   // [B, 2]
    const int*   a     = (const int*)  d_in[1];   // [B, T]
    const float* world = (const float*)d_in[2];   // [B, 2, 64, 64]

    const int B = in_sizes[0] / 2;
    const int T = in_sizes[1] / B;

    float* out_s = (float*)d_out;                       // [B, T+1, 2]
    float* out_r = out_s + (size_t)B * (T + 1) * 2;     // [B, T+1]

    cudaFuncSetAttribute(rollout_fused_kernel,
                         cudaFuncAttributeMaxDynamicSharedMemorySize, SMEM_TOTAL);

    const int grid = (B + NB - 1) / NB;                 // 128
    rollout_fused_kernel<<<grid, NTHREADS, SMEM_TOTAL>>>(s0, a, world,
                                                         out_s, out_r, B, T);
}